// round 13
// baseline (speedup 1.0000x reference)
#include <cuda_runtime.h>
#include <cstdint>

// Problem dims (fixed by the reference)
#define BB 4096   // batch
#define DD 1024   // input dim
#define HH 4096   // hidden dim
#define OO 1000   // output dim

// Eigen-master aarch64 GEBP blocking: kc = 200 (VERIFIED: passes at 9.54e-4)
#define KC 200
#define TK 16     // k-slab per smem stage (folds land on the 8-grid)

typedef unsigned long long u64;

// amax slots: 0=x 1=W0 2=W1 3=W2 4=h1 5=h2
__device__ unsigned g_stats[8];

// Dequantized fp32 tensors (fl(q*scale), bitwise = reference fake-quant)
__device__ float g_a  [BB * DD];
__device__ float g_w0 [HH * DD];
__device__ float g_w1 [HH * HH];
__device__ float g_w2 [OO * HH];
__device__ float g_h  [BB * HH];   // layer output (pre-quant)
__device__ float g_hq [BB * HH];   // fake-quant(h), dequantized fp32

__global__ void k_init() {
    if (threadIdx.x < 8) g_stats[threadIdx.x] = 0u;
}

// ---------------------------------------------------------------------------
// absmax (exact, order-independent)
// ---------------------------------------------------------------------------
__global__ void k_absmax(const float4* __restrict__ t, int n4, int idx) {
    float m = 0.f;
    for (int i = blockIdx.x * blockDim.x + threadIdx.x; i < n4;
         i += gridDim.x * blockDim.x) {
        float4 v = t[i];
        m = fmaxf(m, fmaxf(fmaxf(fabsf(v.x), fabsf(v.y)),
                           fmaxf(fabsf(v.z), fabsf(v.w))));
    }
#pragma unroll
    for (int o = 16; o; o >>= 1)
        m = fmaxf(m, __shfl_xor_sync(0xffffffffu, m, o));
    if ((threadIdx.x & 31) == 0)
        atomicMax(&g_stats[idx], __float_as_uint(m));
}

// ---------------------------------------------------------------------------
// fake-quant -> dequantized fp32 (reference op-for-op; bitwise identical to
// the R12 int8+in-GEMM-dequant path, since (float)(int8)q == q exactly):
//   scale = max(fl(amax/3), 1e-8)
//   q     = clip(round_half_even(fl(t/scale)), -4, 3)
//   out   = fl(q * scale)
// ---------------------------------------------------------------------------
__global__ void k_quantdq(const float4* __restrict__ t, float4* __restrict__ o,
                          int n4, int idx) {
    const float amax  = __uint_as_float(g_stats[idx]);
    const float scale = fmaxf(__fdiv_rn(amax, 3.0f), 1e-8f);
    for (int i = blockIdx.x * blockDim.x + threadIdx.x; i < n4;
         i += gridDim.x * blockDim.x) {
        float4 v = t[i];
        float qa = fminf(fmaxf(rintf(__fdiv_rn(v.x, scale)), -4.f), 3.f);
        float qb = fminf(fmaxf(rintf(__fdiv_rn(v.y, scale)), -4.f), 3.f);
        float qc = fminf(fmaxf(rintf(__fdiv_rn(v.z, scale)), -4.f), 3.f);
        float qd = fminf(fmaxf(rintf(__fdiv_rn(v.w, scale)), -4.f), 3.f);
        float4 r;
        r.x = __fmul_rn(qa, scale); r.y = __fmul_rn(qb, scale);
        r.z = __fmul_rn(qc, scale); r.w = __fmul_rn(qd, scale);
        o[i] = r;
    }
}

// ---------------------------------------------------------------------------
// packed f32x2 helpers: two INDEPENDENT lane-wise fp32 ops per instruction.
// ---------------------------------------------------------------------------
__device__ __forceinline__ u64 pk2(float lo, float hi) {
    u64 r; asm("mov.b64 %0, {%1, %2};" : "=l"(r) : "f"(lo), "f"(hi)); return r;
}
__device__ __forceinline__ void upk2(u64 v, float& lo, float& hi) {
    asm("mov.b64 {%0, %1}, %2;" : "=f"(lo), "=f"(hi) : "l"(v));
}
__device__ __forceinline__ u64 ffma2(u64 a, u64 b, u64 c) {
    u64 r; asm("fma.rn.f32x2 %0, %1, %2, %3;" : "=l"(r) : "l"(a), "l"(b), "l"(c));
    return r;
}
__device__ __forceinline__ u64 fadd2(u64 a, u64 b) {
    u64 r; asm("add.rn.f32x2 %0, %1, %2;" : "=l"(r) : "l"(a), "l"(b));
    return r;
}

// ---------------------------------------------------------------------------
// Eigen-replica fp32 GEMM (v3: fp32 operands, 512 threads, 4x8 micro-tile).
// Arithmetic per output element BITWISE IDENTICAL to R10/R12:
//   fused fp32 FMA chain, ascending k, panels of KC=200 folded C = fl(S+C),
//   then fl(C+bias), optional ReLU. Fused absmax of stored output.
// ---------------------------------------------------------------------------
__global__ __launch_bounds__(512, 1) void k_gemm_eig(
    const float* __restrict__ A, const float* __restrict__ Bw,
    const float* __restrict__ bias, float* __restrict__ C,
    int M, int N, int K, int relu, int iamax)
{
    __shared__ float sA[2][TK][128];   // [buf][k][m]
    __shared__ float sB[2][TK][128];   // [buf][k][n]

    const int tid = threadIdx.x;
    const int tx  = tid & 15;          // 16 col groups (8 cols each)
    const int ty  = tid >> 4;          // 32 row groups (4 rows each)
    const int bm  = blockIdx.y * 128;
    const int bn  = blockIdx.x * 128;
    const int lr  = tid & 127;         // loader row 0..127
    const int lkb = (tid >> 7) * 4;    // loader k base {0,4,8,12}

    const float* Ab = A + (size_t)(bm + lr) * K + lkb;
    const bool bok  = (bn + lr) < N;
    const float* Bb = Bw + (size_t)(bok ? (bn + lr) : 0) * K + lkb;

#define STAGE(b, va, vb) do {                                                  \
    sA[b][lkb + 0][lr] = (va).x; sA[b][lkb + 1][lr] = (va).y;                  \
    sA[b][lkb + 2][lr] = (va).z; sA[b][lkb + 3][lr] = (va).w;                  \
    sB[b][lkb + 0][lr] = (vb).x; sB[b][lkb + 1][lr] = (vb).y;                  \
    sB[b][lkb + 2][lr] = (vb).z; sB[b][lkb + 3][lr] = (vb).w;                  \
    } while (0)

#define FOLD() do {                                                            \
    _Pragma("unroll")                                                          \
    for (int i = 0; i < 4; i++)                                                \
        _Pragma("unroll")                                                      \
        for (int j = 0; j < 4; j++) {                                          \
            Cc[i][j] = fadd2(S[i][j], Cc[i][j]);                               \
            S[i][j]  = 0ull;                                                   \
        } } while (0)

#define BLOCK(b, o) do {                                                       \
    _Pragma("unroll")                                                          \
    for (int kk = (o); kk < (o) + 8; kk++) {                                   \
        const float4 a0 = *reinterpret_cast<const float4*>(                    \
            &sA[b][kk][ty * 4]);                                               \
        const ulonglong2 q0 = *reinterpret_cast<const ulonglong2*>(            \
            &sB[b][kk][tx * 8]);                                               \
        const ulonglong2 q1 = *reinterpret_cast<const ulonglong2*>(            \
            &sB[b][kk][tx * 8 + 4]);                                           \
        u64 b2[4] = {q0.x, q0.y, q1.x, q1.y};                                  \
        float av[4] = {a0.x, a0.y, a0.z, a0.w};                                \
        _Pragma("unroll")                                                      \
        for (int i = 0; i < 4; i++) {                                          \
            u64 a2 = pk2(av[i], av[i]);                                        \
            _Pragma("unroll")                                                  \
            for (int j = 0; j < 4; j++)                                        \
                S[i][j] = ffma2(a2, b2[j], S[i][j]);                           \
        } } } while (0)

    u64 S[4][4], Cc[4][4];
#pragma unroll
    for (int i = 0; i < 4; i++)
#pragma unroll
        for (int j = 0; j < 4; j++) { S[i][j] = 0ull; Cc[i][j] = 0ull; }

    // prologue: stage slab 0
    {
        float4 va = *reinterpret_cast<const float4*>(Ab);
        float4 vb = bok ? *reinterpret_cast<const float4*>(Bb)
                        : make_float4(0.f, 0.f, 0.f, 0.f);
        STAGE(0, va, vb);
    }
    __syncthreads();

    int buf = 0;
    for (int k0 = 0; k0 < K; k0 += TK) {
        // issue next slab's gmem loads (latency hidden by BLOCKs below)
        float4 va = make_float4(0.f, 0.f, 0.f, 0.f);
        float4 vb = va;
        const bool more = (k0 + TK) < K;
        if (more) {
            va = *reinterpret_cast<const float4*>(Ab + k0 + TK);
            if (bok) vb = *reinterpret_cast<const float4*>(Bb + k0 + TK);
        }

        if (k0 && (k0 % KC == 0)) FOLD();
        BLOCK(buf, 0);
        if (((k0 + 8) % KC) == 0) FOLD();
        BLOCK(buf, 8);

        if (more) STAGE(buf ^ 1, va, vb);
        __syncthreads();
        buf ^= 1;
    }
    FOLD();   // final panel

    // Epilogue: fl(C + bias), optional ReLU, store, fused absmax
    float lmax = 0.f;
#pragma unroll
    for (int i = 0; i < 4; i++) {
        const int row = bm + ty * 4 + i;
#pragma unroll
        for (int j = 0; j < 4; j++) {
            float y0, y1;
            upk2(Cc[i][j], y0, y1);
            const int c0 = bn + tx * 8 + j * 2;
            if (c0 < N) {
                float y = __fadd_rn(y0, bias[c0]);
                if (relu) y = fmaxf(y, 0.f);
                C[(size_t)row * N + c0] = y;
                lmax = fmaxf(lmax, fabsf(y));
            }
            if (c0 + 1 < N) {
                float y = __fadd_rn(y1, bias[c0 + 1]);
                if (relu) y = fmaxf(y, 0.f);
                C[(size_t)row * N + c0 + 1] = y;
                lmax = fmaxf(lmax, fabsf(y));
            }
        }
    }
    if (iamax >= 0) {
#pragma unroll
        for (int o = 16; o; o >>= 1)
            lmax = fmaxf(lmax, __shfl_xor_sync(0xffffffffu, lmax, o));
        if ((tid & 31) == 0)
            atomicMax(&g_stats[iamax], __float_as_uint(lmax));
    }
#undef STAGE
#undef FOLD
#undef BLOCK
}

// ---------------------------------------------------------------------------
extern "C" void kernel_launch(void* const* d_in, const int* in_sizes, int n_in,
                              void* d_out, int out_size) {
    const float* x  = (const float*)d_in[0];
    const float* W0 = (const float*)d_in[1];
    const float* b0 = (const float*)d_in[2];
    const float* W1 = (const float*)d_in[3];
    const float* b1 = (const float*)d_in[4];
    const float* W2 = (const float*)d_in[5];
    const float* b2 = (const float*)d_in[6];
    float* out = (float*)d_out;

    void *p_a, *p_w0, *p_w1, *p_w2, *p_h, *p_hq;
    cudaGetSymbolAddress(&p_a,  g_a);
    cudaGetSymbolAddress(&p_w0, g_w0);
    cudaGetSymbolAddress(&p_w1, g_w1);
    cudaGetSymbolAddress(&p_w2, g_w2);
    cudaGetSymbolAddress(&p_h,  g_h);
    cudaGetSymbolAddress(&p_hq, g_hq);

    k_init<<<1, 32>>>();

    k_absmax<<<1024, 256>>>((const float4*)x,  (BB * DD) / 4, 0);
    k_absmax<<<1024, 256>>>((const float4*)W0, (HH * DD) / 4, 1);
    k_absmax<<<2048, 256>>>((const float4*)W1, (HH * HH) / 4, 2);
    k_absmax<<<1024, 256>>>((const float4*)W2, (OO * HH) / 4, 3);

    k_quantdq<<<1024, 256>>>((const float4*)x,  (float4*)p_a,  (BB * DD) / 4, 0);
    k_quantdq<<<1024, 256>>>((const float4*)W0, (float4*)p_w0, (HH * DD) / 4, 1);
    k_quantdq<<<2048, 256>>>((const float4*)W1, (float4*)p_w1, (HH * HH) / 4, 2);
    k_quantdq<<<1024, 256>>>((const float4*)W2, (float4*)p_w2, (OO * HH) / 4, 3);

    dim3 blk(512);
    dim3 g01(HH / 128, BB / 128);            // 32 x 32
    dim3 g2((OO + 127) / 128, BB / 128);     // 8 x 32

    // Layer 0: h = relu(fq(x) @ fq(W0)^T + b0), fused absmax -> slot 4
    k_gemm_eig<<<g01, blk>>>((const float*)p_a, (const float*)p_w0, b0,
                             (float*)p_h, BB, HH, DD, 1, 4);
    k_quantdq<<<2048, 256>>>((const float4*)p_h, (float4*)p_hq, (BB * HH) / 4, 4);

    // Layer 1: h = relu(fq(h) @ fq(W1)^T + b1), fused absmax -> slot 5
    k_gemm_eig<<<g01, blk>>>((const float*)p_hq, (const float*)p_w1, b1,
                             (float*)p_h, BB, HH, HH, 1, 5);
    k_quantdq<<<2048, 256>>>((const float4*)p_h, (float4*)p_hq, (BB * HH) / 4, 5);

    // Layer 2: out = fq(h) @ fq(W2)^T + b2 (no relu, no further quant)
    k_gemm_eig<<<g2, blk>>>((const float*)p_hq, (const float*)p_w2, b2,
                            out, BB, OO, HH, 0, -1);
}

// round 15
// speedup vs baseline: 1.0415x; 1.0415x over previous
#include <cuda_runtime.h>
#include <cstdint>

// Problem dims (fixed by the reference)
#define BB 4096   // batch
#define DD 1024   // input dim
#define HH 4096   // hidden dim
#define OO 1000   // output dim

// Eigen-master aarch64 GEBP blocking: kc = 200 (VERIFIED: passes at 9.54e-4)
#define KC 200
#define TK 16     // k-slab per smem stage (folds land on the 8-grid)

typedef unsigned long long u64;

// amax slots: 0=x 1=W0 2=W1 3=W2 4=h1 5=h2
__device__ unsigned g_stats[8];

// int8 quantized tensors + fp32 hidden activations
__device__ int8_t g_qx [BB * DD];
__device__ int8_t g_qw0[HH * DD];
__device__ int8_t g_qw1[HH * HH];
__device__ int8_t g_qw2[OO * HH];
__device__ float  g_h  [BB * HH];
__device__ int8_t g_qh [BB * HH];

__global__ void k_init() {
    if (threadIdx.x < 8) g_stats[threadIdx.x] = 0u;
}

// ---------------------------------------------------------------------------
// absmax (exact, order-independent)
// ---------------------------------------------------------------------------
__global__ void k_absmax(const float4* __restrict__ t, int n4, int idx) {
    float m = 0.f;
    for (int i = blockIdx.x * blockDim.x + threadIdx.x; i < n4;
         i += gridDim.x * blockDim.x) {
        float4 v = t[i];
        m = fmaxf(m, fmaxf(fmaxf(fabsf(v.x), fabsf(v.y)),
                           fmaxf(fabsf(v.z), fabsf(v.w))));
    }
#pragma unroll
    for (int o = 16; o; o >>= 1)
        m = fmaxf(m, __shfl_xor_sync(0xffffffffu, m, o));
    if ((threadIdx.x & 31) == 0)
        atomicMax(&g_stats[idx], __float_as_uint(m));
}

// ---------------------------------------------------------------------------
// quantize: q = clip(round_half_even(fl(t / scale)), -4, 3)  (ref op-for-op)
// ---------------------------------------------------------------------------
__global__ void k_quant(const float4* __restrict__ t, char4* __restrict__ q,
                        int n4, int idx) {
    const float amax  = __uint_as_float(g_stats[idx]);
    const float scale = fmaxf(__fdiv_rn(amax, 3.0f), 1e-8f);
    for (int i = blockIdx.x * blockDim.x + threadIdx.x; i < n4;
         i += gridDim.x * blockDim.x) {
        float4 v = t[i];
        int a = (int)fminf(fmaxf(rintf(__fdiv_rn(v.x, scale)), -4.f), 3.f);
        int b = (int)fminf(fmaxf(rintf(__fdiv_rn(v.y, scale)), -4.f), 3.f);
        int c = (int)fminf(fmaxf(rintf(__fdiv_rn(v.z, scale)), -4.f), 3.f);
        int d = (int)fminf(fmaxf(rintf(__fdiv_rn(v.w, scale)), -4.f), 3.f);
        q[i] = make_char4((signed char)a, (signed char)b,
                          (signed char)c, (signed char)d);
    }
}

// ---------------------------------------------------------------------------
// packed f32x2 helpers: two INDEPENDENT lane-wise fp32 ops per instruction.
// ---------------------------------------------------------------------------
__device__ __forceinline__ u64 pk2(float lo, float hi) {
    u64 r; asm("mov.b64 %0, {%1, %2};" : "=l"(r) : "f"(lo), "f"(hi)); return r;
}
__device__ __forceinline__ void upk2(u64 v, float& lo, float& hi) {
    asm("mov.b64 {%0, %1}, %2;" : "=f"(lo), "=f"(hi) : "l"(v));
}
__device__ __forceinline__ u64 ffma2(u64 a, u64 b, u64 c) {
    u64 r; asm("fma.rn.f32x2 %0, %1, %2, %3;" : "=l"(r) : "l"(a), "l"(b), "l"(c));
    return r;
}
__device__ __forceinline__ u64 fadd2(u64 a, u64 b) {
    u64 r; asm("add.rn.f32x2 %0, %1, %2;" : "=l"(r) : "l"(a), "l"(b));
    return r;
}

// ---------------------------------------------------------------------------
// Eigen-replica fp32 GEMM (v4: int8 operands, 512 threads, role-split stage,
// 4x8 micro-tile). Arithmetic per output element BITWISE IDENTICAL to R10/R12:
//   fused fp32 FMA chain, ascending k, panels of KC=200 folded C = fl(S+C),
//   then fl(C+bias), optional ReLU. Operands fl(q*scale). Fused absmax.
// ---------------------------------------------------------------------------
__global__ __launch_bounds__(512, 1) void k_gemm_eig(
    const int8_t* __restrict__ A, const int8_t* __restrict__ Bw,
    const float* __restrict__ bias, float* __restrict__ C,
    int M, int N, int K, int ia, int ib, int relu, int iamax)
{
    __shared__ float sA[2][TK][128];   // [buf][k][m]
    __shared__ float sB[2][TK][128];   // [buf][k][n]

    const int tid = threadIdx.x;
    const int tx  = tid & 15;          // 16 col groups (8 cols each)
    const int ty  = tid >> 4;          // 32 row groups (4 rows each)
    const int bm  = blockIdx.y * 128;
    const int bn  = blockIdx.x * 128;

    // staging role: threads 0-255 stage A, 256-511 stage B
    const int role = tid >> 8;            // 0 = A, 1 = B
    const int slr  = tid & 127;           // staged row 0..127
    const int skb  = ((tid >> 7) & 1) * 8;// staged k base {0,8}

    const float sav = fmaxf(__fdiv_rn(__uint_as_float(g_stats[ia]), 3.0f), 1e-8f);
    const float sbv = fmaxf(__fdiv_rn(__uint_as_float(g_stats[ib]), 3.0f), 1e-8f);
    const float sc  = role ? sbv : sav;

    bool ok = true;
    const int8_t* Sp;
    if (role == 0) {
        Sp = A + (size_t)(bm + slr) * K + skb;
    } else {
        ok = (bn + slr) < N;
        Sp = Bw + (size_t)(ok ? (bn + slr) : 0) * K + skb;
    }

#define STAGE(b, r) do {                                                       \
    unsigned lo = (unsigned)(r), hi = (unsigned)((r) >> 32);                   \
    float* d = role ? &sB[b][skb][slr] : &sA[b][skb][slr];                     \
    d[0 * 128] = __fmul_rn((float)(signed char)(lo      ), sc);                \
    d[1 * 128] = __fmul_rn((float)(signed char)(lo >>  8), sc);                \
    d[2 * 128] = __fmul_rn((float)(signed char)(lo >> 16), sc);                \
    d[3 * 128] = __fmul_rn((float)(signed char)(lo >> 24), sc);                \
    d[4 * 128] = __fmul_rn((float)(signed char)(hi      ), sc);                \
    d[5 * 128] = __fmul_rn((float)(signed char)(hi >>  8), sc);                \
    d[6 * 128] = __fmul_rn((float)(signed char)(hi >> 16), sc);                \
    d[7 * 128] = __fmul_rn((float)(signed char)(hi >> 24), sc);                \
    } while (0)

#define FOLD() do {                                                            \
    _Pragma("unroll")                                                          \
    for (int i = 0; i < 4; i++)                                                \
        _Pragma("unroll")                                                      \
        for (int j = 0; j < 4; j++) {                                          \
            Cc[i][j] = fadd2(S[i][j], Cc[i][j]);                               \
            S[i][j]  = 0ull;                                                   \
        } } while (0)

#define BLOCK(b, o) do {                                                       \
    _Pragma("unroll")                                                          \
    for (int kk = (o); kk < (o) + 8; kk++) {                                   \
        const float4 a0 = *reinterpret_cast<const float4*>(                    \
            &sA[b][kk][ty * 4]);                                               \
        const ulonglong2 q0 = *reinterpret_cast<const ulonglong2*>(            \
            &sB[b][kk][tx * 8]);                                               \
        const ulonglong2 q1 = *reinterpret_cast<const ulonglong2*>(            \
            &sB[b][kk][tx * 8 + 4]);                                           \
        u64 b2[4] = {q0.x, q0.y, q1.x, q1.y};                                  \
        float av[4] = {a0.x, a0.y, a0.z, a0.w};                                \
        _Pragma("unroll")                                                      \
        for (int i = 0; i < 4; i++) {                                          \
            u64 a2 = pk2(av[i], av[i]);                                        \
            _Pragma("unroll")                                                  \
            for (int j = 0; j < 4; j++)                                        \
                S[i][j] = ffma2(a2, b2[j], S[i][j]);                           \
        } } } while (0)

    u64 S[4][4], Cc[4][4];
#pragma unroll
    for (int i = 0; i < 4; i++)
#pragma unroll
        for (int j = 0; j < 4; j++) { S[i][j] = 0ull; Cc[i][j] = 0ull; }

    // prologue: stage slab 0
    {
        u64 r = ok ? *reinterpret_cast<const u64*>(Sp) : 0ull;
        STAGE(0, r);
    }
    __syncthreads();

    int buf = 0;
    for (int k0 = 0; k0 < K; k0 += TK) {
        // issue next slab's gmem load (latency hidden by BLOCKs below)
        u64 r = 0ull;
        const bool more = (k0 + TK) < K;
        if (more && ok)
            r = *reinterpret_cast<const u64*>(Sp + k0 + TK);

        if (k0 && (k0 % KC == 0)) FOLD();
        BLOCK(buf, 0);
        if (((k0 + 8) % KC) == 0) FOLD();
        BLOCK(buf, 8);

        if (more) STAGE(buf ^ 1, r);
        __syncthreads();
        buf ^= 1;
    }
    FOLD();   // final panel

    // Epilogue: fl(C + bias), optional ReLU, store, fused absmax
    float lmax = 0.f;
#pragma unroll
    for (int i = 0; i < 4; i++) {
        const int row = bm + ty * 4 + i;
#pragma unroll
        for (int j = 0; j < 4; j++) {
            float y0, y1;
            upk2(Cc[i][j], y0, y1);
            const int c0 = bn + tx * 8 + j * 2;
            if (c0 < N) {
                float y = __fadd_rn(y0, bias[c0]);
                if (relu) y = fmaxf(y, 0.f);
                C[(size_t)row * N + c0] = y;
                lmax = fmaxf(lmax, fabsf(y));
            }
            if (c0 + 1 < N) {
                float y = __fadd_rn(y1, bias[c0 + 1]);
                if (relu) y = fmaxf(y, 0.f);
                C[(size_t)row * N + c0 + 1] = y;
                lmax = fmaxf(lmax, fabsf(y));
            }
        }
    }
    if (iamax >= 0) {
#pragma unroll
        for (int o = 16; o; o >>= 1)
            lmax = fmaxf(lmax, __shfl_xor_sync(0xffffffffu, lmax, o));
        if ((tid & 31) == 0)
            atomicMax(&g_stats[iamax], __float_as_uint(lmax));
    }
#undef STAGE
#undef FOLD
#undef BLOCK
}

// ---------------------------------------------------------------------------
extern "C" void kernel_launch(void* const* d_in, const int* in_sizes, int n_in,
                              void* d_out, int out_size) {
    const float* x  = (const float*)d_in[0];
    const float* W0 = (const float*)d_in[1];
    const float* b0 = (const float*)d_in[2];
    const float* W1 = (const float*)d_in[3];
    const float* b1 = (const float*)d_in[4];
    const float* W2 = (const float*)d_in[5];
    const float* b2 = (const float*)d_in[6];
    float* out = (float*)d_out;

    void *p_qx, *p_qw0, *p_qw1, *p_qw2, *p_h, *p_qh;
    cudaGetSymbolAddress(&p_qx,  g_qx);
    cudaGetSymbolAddress(&p_qw0, g_qw0);
    cudaGetSymbolAddress(&p_qw1, g_qw1);
    cudaGetSymbolAddress(&p_qw2, g_qw2);
    cudaGetSymbolAddress(&p_h,   g_h);
    cudaGetSymbolAddress(&p_qh,  g_qh);

    k_init<<<1, 32>>>();

    k_absmax<<<1024, 256>>>((const float4*)x,  (BB * DD) / 4, 0);
    k_absmax<<<1024, 256>>>((const float4*)W0, (HH * DD) / 4, 1);
    k_absmax<<<2048, 256>>>((const float4*)W1, (HH * HH) / 4, 2);
    k_absmax<<<1024, 256>>>((const float4*)W2, (OO * HH) / 4, 3);

    k_quant<<<1024, 256>>>((const float4*)x,  (char4*)p_qx,  (BB * DD) / 4, 0);
    k_quant<<<1024, 256>>>((const float4*)W0, (char4*)p_qw0, (HH * DD) / 4, 1);
    k_quant<<<2048, 256>>>((const float4*)W1, (char4*)p_qw1, (HH * HH) / 4, 2);
    k_quant<<<1024, 256>>>((const float4*)W2, (char4*)p_qw2, (OO * HH) / 4, 3);

    dim3 blk(512);
    dim3 g01(HH / 128, BB / 128);            // 32 x 32
    dim3 g2((OO + 127) / 128, BB / 128);     // 8 x 32

    // Layer 0: h = relu(fq(x) @ fq(W0)^T + b0), fused absmax -> slot 4
    k_gemm_eig<<<g01, blk>>>((const int8_t*)p_qx, (const int8_t*)p_qw0, b0,
                             (float*)p_h, BB, HH, DD, 0, 1, 1, 4);
    k_quant<<<2048, 256>>>((const float4*)p_h, (char4*)p_qh, (BB * HH) / 4, 4);

    // Layer 1: h = relu(fq(h) @ fq(W1)^T + b1), fused absmax -> slot 5
    k_gemm_eig<<<g01, blk>>>((const int8_t*)p_qh, (const int8_t*)p_qw1, b1,
                             (float*)p_h, BB, HH, HH, 4, 2, 1, 5);
    k_quant<<<2048, 256>>>((const float4*)p_h, (char4*)p_qh, (BB * HH) / 4, 5);

    // Layer 2: out = fq(h) @ fq(W2)^T + b2 (no relu, no further quant)
    k_gemm_eig<<<g2, blk>>>((const int8_t*)p_qh, (const int8_t*)p_qw2, b2,
                            out, BB, OO, HH, 5, 3, 0, -1);
}

// round 16
// speedup vs baseline: 1.3277x; 1.2749x over previous
#include <cuda_runtime.h>
#include <cstdint>

// Problem dims (fixed by the reference)
#define BB 4096   // batch
#define DD 1024   // input dim
#define HH 4096   // hidden dim
#define OO 1000   // output dim

// Eigen-master aarch64 GEBP blocking: kc = 200 (VERIFIED: passes at 9.54e-4)
#define KC 200
#define TK 16     // k-slab per smem stage (folds land on the 8-grid)

typedef unsigned long long u64;

// amax slots: 0=x 1=W0 2=W1 3=W2 4=h1 5=h2
__device__ unsigned g_stats[8];

// int8 quantized tensors + fp32 hidden activations
__device__ int8_t g_qx [BB * DD];
__device__ int8_t g_qw0[HH * DD];
__device__ int8_t g_qw1[HH * HH];
__device__ int8_t g_qw2[OO * HH];
__device__ float  g_h  [BB * HH];
__device__ int8_t g_qh [BB * HH];

__global__ void k_init() {
    if (threadIdx.x < 8) g_stats[threadIdx.x] = 0u;
}

// ---------------------------------------------------------------------------
// absmax (exact, order-independent)
// ---------------------------------------------------------------------------
__global__ void k_absmax(const float4* __restrict__ t, int n4, int idx) {
    float m = 0.f;
    for (int i = blockIdx.x * blockDim.x + threadIdx.x; i < n4;
         i += gridDim.x * blockDim.x) {
        float4 v = t[i];
        m = fmaxf(m, fmaxf(fmaxf(fabsf(v.x), fabsf(v.y)),
                           fmaxf(fabsf(v.z), fabsf(v.w))));
    }
#pragma unroll
    for (int o = 16; o; o >>= 1)
        m = fmaxf(m, __shfl_xor_sync(0xffffffffu, m, o));
    if ((threadIdx.x & 31) == 0)
        atomicMax(&g_stats[idx], __float_as_uint(m));
}

// ---------------------------------------------------------------------------
// quantize: q = clip(round_half_even(fl(t / scale)), -4, 3)  (ref op-for-op)
// ---------------------------------------------------------------------------
__global__ void k_quant(const float4* __restrict__ t, char4* __restrict__ q,
                        int n4, int idx) {
    const float amax  = __uint_as_float(g_stats[idx]);
    const float scale = fmaxf(__fdiv_rn(amax, 3.0f), 1e-8f);
    for (int i = blockIdx.x * blockDim.x + threadIdx.x; i < n4;
         i += gridDim.x * blockDim.x) {
        float4 v = t[i];
        int a = (int)fminf(fmaxf(rintf(__fdiv_rn(v.x, scale)), -4.f), 3.f);
        int b = (int)fminf(fmaxf(rintf(__fdiv_rn(v.y, scale)), -4.f), 3.f);
        int c = (int)fminf(fmaxf(rintf(__fdiv_rn(v.z, scale)), -4.f), 3.f);
        int d = (int)fminf(fmaxf(rintf(__fdiv_rn(v.w, scale)), -4.f), 3.f);
        q[i] = make_char4((signed char)a, (signed char)b,
                          (signed char)c, (signed char)d);
    }
}

// ---------------------------------------------------------------------------
// packed f32x2 helpers: two INDEPENDENT lane-wise fp32 ops per instruction.
// ---------------------------------------------------------------------------
__device__ __forceinline__ u64 pk2(float lo, float hi) {
    u64 r; asm("mov.b64 %0, {%1, %2};" : "=l"(r) : "f"(lo), "f"(hi)); return r;
}
__device__ __forceinline__ void upk2(u64 v, float& lo, float& hi) {
    asm("mov.b64 {%0, %1}, %2;" : "=f"(lo), "=f"(hi) : "l"(v));
}
__device__ __forceinline__ u64 ffma2(u64 a, u64 b, u64 c) {
    u64 r; asm("fma.rn.f32x2 %0, %1, %2, %3;" : "=l"(r) : "l"(a), "l"(b), "l"(c));
    return r;
}
__device__ __forceinline__ u64 fadd2(u64 a, u64 b) {
    u64 r; asm("add.rn.f32x2 %0, %1, %2;" : "=l"(r) : "l"(a), "l"(b));
    return r;
}

// ---------------------------------------------------------------------------
// Eigen-replica fp32 GEMM (v5 = verified R12 structure; sA holds duplicated
// {v,v} u64 pairs so the mainloop needs no register-duplication MOVs).
// Arithmetic per output element BITWISE IDENTICAL to R10/R12:
//   fused fp32 FMA chain, ascending k, panels of KC=200 folded C = fl(S+C),
//   then fl(C+bias), optional ReLU. Operands fl(q*scale). Fused absmax.
// ---------------------------------------------------------------------------
__global__ __launch_bounds__(256, 1) void k_gemm_eig(
    const int8_t* __restrict__ A, const int8_t* __restrict__ Bw,
    const float* __restrict__ bias, float* __restrict__ C,
    int M, int N, int K, int ia, int ib, int relu, int iamax)
{
    __shared__ u64   sA[2][TK][128];   // [buf][k][m], value duplicated {v,v}
    __shared__ float sB[2][TK][128];   // [buf][k][n]

    const int tid = threadIdx.x;
    const int tx  = tid & 15;          // 16 col groups (8 cols each)
    const int ty  = tid >> 4;          // 16 row groups (8 rows each)
    const int bm  = blockIdx.y * 128;
    const int bn  = blockIdx.x * 128;
    const int lr  = tid >> 1;          // loader row 0..127
    const int lkb = (tid & 1) * 8;     // loader k base {0,8}

    const float sa = fmaxf(__fdiv_rn(__uint_as_float(g_stats[ia]), 3.0f), 1e-8f);
    const float sb = fmaxf(__fdiv_rn(__uint_as_float(g_stats[ib]), 3.0f), 1e-8f);

    const int8_t* Ab = A + (size_t)(bm + lr) * K + lkb;
    const bool bok   = (bn + lr) < N;
    const int8_t* Bb = Bw + (size_t)(bok ? (bn + lr) : 0) * K + lkb;

#define STAGE(b, ra, rb) do {                                                  \
    unsigned alo = (unsigned)(ra), ahi = (unsigned)((ra) >> 32);               \
    unsigned blo = (unsigned)(rb), bhi = (unsigned)((rb) >> 32);               \
    float fa, fb;                                                              \
    fa = __fmul_rn((float)(signed char)(alo      ), sa);                       \
    fb = __fmul_rn((float)(signed char)(blo      ), sb);                       \
    sA[b][lkb + 0][lr] = pk2(fa, fa); sB[b][lkb + 0][lr] = fb;                 \
    fa = __fmul_rn((float)(signed char)(alo >>  8), sa);                       \
    fb = __fmul_rn((float)(signed char)(blo >>  8), sb);                       \
    sA[b][lkb + 1][lr] = pk2(fa, fa); sB[b][lkb + 1][lr] = fb;                 \
    fa = __fmul_rn((float)(signed char)(alo >> 16), sa);                       \
    fb = __fmul_rn((float)(signed char)(blo >> 16), sb);                       \
    sA[b][lkb + 2][lr] = pk2(fa, fa); sB[b][lkb + 2][lr] = fb;                 \
    fa = __fmul_rn((float)(signed char)(alo >> 24), sa);                       \
    fb = __fmul_rn((float)(signed char)(blo >> 24), sb);                       \
    sA[b][lkb + 3][lr] = pk2(fa, fa); sB[b][lkb + 3][lr] = fb;                 \
    fa = __fmul_rn((float)(signed char)(ahi      ), sa);                       \
    fb = __fmul_rn((float)(signed char)(bhi      ), sb);                       \
    sA[b][lkb + 4][lr] = pk2(fa, fa); sB[b][lkb + 4][lr] = fb;                 \
    fa = __fmul_rn((float)(signed char)(ahi >>  8), sa);                       \
    fb = __fmul_rn((float)(signed char)(bhi >>  8), sb);                       \
    sA[b][lkb + 5][lr] = pk2(fa, fa); sB[b][lkb + 5][lr] = fb;                 \
    fa = __fmul_rn((float)(signed char)(ahi >> 16), sa);                       \
    fb = __fmul_rn((float)(signed char)(bhi >> 16), sb);                       \
    sA[b][lkb + 6][lr] = pk2(fa, fa); sB[b][lkb + 6][lr] = fb;                 \
    fa = __fmul_rn((float)(signed char)(ahi >> 24), sa);                       \
    fb = __fmul_rn((float)(signed char)(bhi >> 24), sb);                       \
    sA[b][lkb + 7][lr] = pk2(fa, fa); sB[b][lkb + 7][lr] = fb;                 \
    } while (0)

#define FOLD() do {                                                            \
    _Pragma("unroll")                                                          \
    for (int i = 0; i < 8; i++)                                                \
        _Pragma("unroll")                                                      \
        for (int j = 0; j < 4; j++) {                                          \
            Cc[i][j] = fadd2(S[i][j], Cc[i][j]);                               \
            S[i][j]  = 0ull;                                                   \
        } } while (0)

#define BLOCK(b, o) do {                                                       \
    _Pragma("unroll")                                                          \
    for (int kk = (o); kk < (o) + 8; kk++) {                                   \
        const ulonglong2 p0 = *reinterpret_cast<const ulonglong2*>(            \
            &sA[b][kk][ty * 8]);                                               \
        const ulonglong2 p1 = *reinterpret_cast<const ulonglong2*>(            \
            &sA[b][kk][ty * 8 + 2]);                                           \
        const ulonglong2 p2 = *reinterpret_cast<const ulonglong2*>(            \
            &sA[b][kk][ty * 8 + 4]);                                           \
        const ulonglong2 p3 = *reinterpret_cast<const ulonglong2*>(            \
            &sA[b][kk][ty * 8 + 6]);                                           \
        const ulonglong2 q0 = *reinterpret_cast<const ulonglong2*>(            \
            &sB[b][kk][tx * 8]);                                               \
        const ulonglong2 q1 = *reinterpret_cast<const ulonglong2*>(            \
            &sB[b][kk][tx * 8 + 4]);                                           \
        u64 a2[8] = {p0.x, p0.y, p1.x, p1.y, p2.x, p2.y, p3.x, p3.y};          \
        u64 b2[4] = {q0.x, q0.y, q1.x, q1.y};                                  \
        _Pragma("unroll")                                                      \
        for (int i = 0; i < 8; i++)                                            \
            _Pragma("unroll")                                                  \
            for (int j = 0; j < 4; j++)                                        \
                S[i][j] = ffma2(a2[i], b2[j], S[i][j]);                        \
        } } while (0)

    u64 S[8][4], Cc[8][4];
#pragma unroll
    for (int i = 0; i < 8; i++)
#pragma unroll
        for (int j = 0; j < 4; j++) { S[i][j] = 0ull; Cc[i][j] = 0ull; }

    // prologue: stage slab 0
    {
        u64 ra = *reinterpret_cast<const u64*>(Ab);
        u64 rb = bok ? *reinterpret_cast<const u64*>(Bb) : 0ull;
        STAGE(0, ra, rb);
    }
    __syncthreads();

    int buf = 0;
    for (int k0 = 0; k0 < K; k0 += TK) {
        // issue next slab's gmem loads (latency hidden by BLOCKs below)
        u64 ra = 0ull, rb = 0ull;
        const bool more = (k0 + TK) < K;
        if (more) {
            ra = *reinterpret_cast<const u64*>(Ab + k0 + TK);
            rb = bok ? *reinterpret_cast<const u64*>(Bb + k0 + TK) : 0ull;
        }

        if (k0 && (k0 % KC == 0)) FOLD();
        BLOCK(buf, 0);
        if (((k0 + 8) % KC) == 0) FOLD();
        BLOCK(buf, 8);

        if (more) STAGE(buf ^ 1, ra, rb);
        __syncthreads();
        buf ^= 1;
    }
    FOLD();   // final panel

    // Epilogue: fl(C + bias), optional ReLU, store, fused absmax
    float lmax = 0.f;
#pragma unroll
    for (int i = 0; i < 8; i++) {
        const int row = bm + ty * 8 + i;
#pragma unroll
        for (int j = 0; j < 4; j++) {
            float y0, y1;
            upk2(Cc[i][j], y0, y1);
            const int c0 = bn + tx * 8 + j * 2;
            if (c0 < N) {
                float y = __fadd_rn(y0, bias[c0]);
                if (relu) y = fmaxf(y, 0.f);
                C[(size_t)row * N + c0] = y;
                lmax = fmaxf(lmax, fabsf(y));
            }
            if (c0 + 1 < N) {
                float y = __fadd_rn(y1, bias[c0 + 1]);
                if (relu) y = fmaxf(y, 0.f);
                C[(size_t)row * N + c0 + 1] = y;
                lmax = fmaxf(lmax, fabsf(y));
            }
        }
    }
    if (iamax >= 0) {
#pragma unroll
        for (int o = 16; o; o >>= 1)
            lmax = fmaxf(lmax, __shfl_xor_sync(0xffffffffu, lmax, o));
        if ((tid & 31) == 0)
            atomicMax(&g_stats[iamax], __float_as_uint(lmax));
    }
#undef STAGE
#undef FOLD
#undef BLOCK
}

// ---------------------------------------------------------------------------
extern "C" void kernel_launch(void* const* d_in, const int* in_sizes, int n_in,
                              void* d_out, int out_size) {
    const float* x  = (const float*)d_in[0];
    const float* W0 = (const float*)d_in[1];
    const float* b0 = (const float*)d_in[2];
    const float* W1 = (const float*)d_in[3];
    const float* b1 = (const float*)d_in[4];
    const float* W2 = (const float*)d_in[5];
    const float* b2 = (const float*)d_in[6];
    float* out = (float*)d_out;

    void *p_qx, *p_qw0, *p_qw1, *p_qw2, *p_h, *p_qh;
    cudaGetSymbolAddress(&p_qx,  g_qx);
    cudaGetSymbolAddress(&p_qw0, g_qw0);
    cudaGetSymbolAddress(&p_qw1, g_qw1);
    cudaGetSymbolAddress(&p_qw2, g_qw2);
    cudaGetSymbolAddress(&p_h,   g_h);
    cudaGetSymbolAddress(&p_qh,  g_qh);

    dim3 blk(256);
    dim3 g01(HH / 128, BB / 128);            // 32 x 32
    dim3 g2((OO + 127) / 128, BB / 128);     // 8 x 32

    // Launch order arranged so GEMM0 is the 6th launch (ncu -s 5 window).
    k_init<<<1, 32>>>();                                                 // 1
    k_absmax<<<1024, 256>>>((const float4*)x,  (BB * DD) / 4, 0);        // 2
    k_absmax<<<1024, 256>>>((const float4*)W0, (HH * DD) / 4, 1);        // 3
    k_quant<<<1024, 256>>>((const float4*)x,  (char4*)p_qx,  (BB * DD) / 4, 0);  // 4
    k_quant<<<1024, 256>>>((const float4*)W0, (char4*)p_qw0, (HH * DD) / 4, 1);  // 5

    // Layer 0: h = relu(fq(x) @ fq(W0)^T + b0), fused absmax -> slot 4
    k_gemm_eig<<<g01, blk>>>((const int8_t*)p_qx, (const int8_t*)p_qw0, b0,      // 6
                             (float*)p_h, BB, HH, DD, 0, 1, 1, 4);

    k_absmax<<<2048, 256>>>((const float4*)W1, (HH * HH) / 4, 2);        // 7
    k_quant<<<2048, 256>>>((const float4*)W1, (char4*)p_qw1, (HH * HH) / 4, 2);  // 8
    k_quant<<<2048, 256>>>((const float4*)p_h, (char4*)p_qh, (BB * HH) / 4, 4);  // 9

    // Layer 1: h = relu(fq(h) @ fq(W1)^T + b1), fused absmax -> slot 5
    k_gemm_eig<<<g01, blk>>>((const int8_t*)p_qh, (const int8_t*)p_qw1, b1,      // 10
                             (float*)p_h, BB, HH, HH, 4, 2, 1, 5);

    k_absmax<<<1024, 256>>>((const float4*)W2, (OO * HH) / 4, 3);        // 11
    k_quant<<<1024, 256>>>((const float4*)W2, (char4*)p_qw2, (OO * HH) / 4, 3);  // 12
    k_quant<<<2048, 256>>>((const float4*)p_h, (char4*)p_qh, (BB * HH) / 4, 5);  // 13

    // Layer 2: out = fq(h) @ fq(W2)^T + b2 (no relu, no further quant)
    k_gemm_eig<<<g2, blk>>>((const int8_t*)p_qh, (const int8_t*)p_qw2, b2,       // 14
                            out, BB, OO, HH, 5, 3, 0, -1);
}